// round 15
// baseline (speedup 1.0000x reference)
#include <cuda_runtime.h>
#include <cstdint>

// Problem: B=32, N=8192, DIM=256, M=1228
//   in0: x            [B, N, DIM] float32
//   in1: mask_indices [B, M]      int32
//   in2: emb_mask     [1, DIM]    float32
// out: masked_x [B*N*DIM] floats (+ mask_indices as floats if room).

#define DIM      256
#define N_FIX    8192
#define ROWS_PB  64     // rows per tile; 64 flags = 2 uint32
#define THREADS  256
#define UNROLL   8      // 8 float4 in flight per thread
#define GRID     592    // 148 SMs x 4 blocks: exactly one wave (persistent)

__global__ void __launch_bounds__(THREADS, 4)
fused_mask_kernel(const float* __restrict__ x,
                  const int*   __restrict__ mask_indices,
                  const float* __restrict__ emb_mask,
                  float*       __restrict__ out,
                  float*       __restrict__ out_idx,   // may be null
                  int M, int blocks_per_batch, int n_tiles)
{
    __shared__ uint32_t fl[ROWS_PB / 32];   // 2 words

    const int tid = threadIdx.x;

    const int sub  = tid >> 6;        // 0..3: row lane within a group of 4 rows
    const int col4 = tid & 63;        // float4 lane within row
    const float4 emb = reinterpret_cast<const float4*>(emb_mask)[col4];

    // Persistent tile loop: one wave, no inter-wave drain.
    for (int t = blockIdx.x; t < n_tiles; t += GRID) {
        const int b   = t / blocks_per_batch;
        const int blk = t % blocks_per_batch;
        const int r0  = blk * ROWS_PB;

        // clear flags (safe: prior tile's main loop uses register copies only)
        if (tid < ROWS_PB / 32) fl[tid] = 0;
        __syncthreads();

        // Vectorized scan of this batch's indices (int4 = 4 per load).
        const int* idx_row = mask_indices + (size_t)b * M;
        const int M4 = M >> 2;                       // 307 for M=1228
        const int4* idx4 = reinterpret_cast<const int4*>(idx_row);
        const bool emit = (blk == 0) && (out_idx != nullptr);

        for (int i = tid; i < M4; i += THREADS) {
            int4 q = __ldg(&idx4[i]);
            int l0 = q.x - r0, l1 = q.y - r0, l2 = q.z - r0, l3 = q.w - r0;
            if ((unsigned)l0 < (unsigned)ROWS_PB) atomicOr(&fl[l0 >> 5], 1u << (l0 & 31));
            if ((unsigned)l1 < (unsigned)ROWS_PB) atomicOr(&fl[l1 >> 5], 1u << (l1 & 31));
            if ((unsigned)l2 < (unsigned)ROWS_PB) atomicOr(&fl[l2 >> 5], 1u << (l2 & 31));
            if ((unsigned)l3 < (unsigned)ROWS_PB) atomicOr(&fl[l3 >> 5], 1u << (l3 & 31));
            if (emit) {
                float4 f = make_float4((float)q.x, (float)q.y, (float)q.z, (float)q.w);
                reinterpret_cast<float4*>(out_idx + (size_t)b * M)[i] = f;
            }
        }
        for (int i = (M4 << 2) + tid; i < M; i += THREADS) {
            int idx = idx_row[i];
            int local = idx - r0;
            if ((unsigned)local < (unsigned)ROWS_PB)
                atomicOr(&fl[local >> 5], 1u << (local & 31));
            if (emit) out_idx[(size_t)b * M + i] = (float)idx;
        }
        __syncthreads();

        // bitmask into registers (broadcast LDS, conflict-free)
        uint32_t fw[ROWS_PB / 32];
        #pragma unroll
        for (int w = 0; w < ROWS_PB / 32; ++w) fw[w] = fl[w];

        const size_t base = ((size_t)b * N_FIX + r0) * (DIM / 4);
        const float4* __restrict__ src = reinterpret_cast<const float4*>(x) + base;
        float4*       __restrict__ dst = reinterpret_cast<float4*>(out)     + base;

        // 16 row-iterations: two direct 8-wide load/store batches (max MLP).
        #pragma unroll
        for (int it = 0; it < ROWS_PB / 4; it += UNROLL) {
            float4 v[UNROLL];
            #pragma unroll
            for (int u = 0; u < UNROLL; ++u) {
                const int row = (it + u) * 4 + sub;
                const size_t off = (size_t)row * (DIM / 4) + col4;
                const bool masked = (fw[row >> 5] >> (row & 31)) & 1u;
                v[u] = masked ? emb : __ldcs(&src[off]);
            }
            #pragma unroll
            for (int u = 0; u < UNROLL; ++u) {
                const int row = (it + u) * 4 + sub;
                const size_t off = (size_t)row * (DIM / 4) + col4;
                __stcs(&dst[off], v[u]);
            }
        }
        // no sync needed here: next iteration's flag-clear is ordered by the
        // __syncthreads() after it, and main loop reads only register copies.
    }
}

extern "C" void kernel_launch(void* const* d_in, const int* in_sizes, int n_in,
                              void* d_out, int out_size)
{
    const float* x            = (const float*)d_in[0];
    const int*   mask_indices = (const int*)d_in[1];
    const float* emb_mask     = (const float*)d_in[2];
    float*       out          = (float*)d_out;

    const int x_elems   = in_sizes[0];          // B*N*DIM
    const int idx_elems = in_sizes[1];          // B*M
    const int BN        = x_elems / DIM;        // B*N
    const int B         = BN / N_FIX;
    const int M         = idx_elems / B;

    float* out_idx = (out_size >= x_elems + idx_elems)
                   ? (out + x_elems) : nullptr;

    const int blocks_per_batch = N_FIX / ROWS_PB;   // 128
    const int n_tiles = B * blocks_per_batch;       // 4096

    fused_mask_kernel<<<GRID, THREADS>>>(
        x, mask_indices, emb_mask, out, out_idx, M, blocks_per_batch, n_tiles);
}

// round 16
// speedup vs baseline: 1.1216x; 1.1216x over previous
#include <cuda_runtime.h>
#include <cstdint>

// Problem: B=32, N=8192, DIM=256, M=1228
//   in0: x            [B, N, DIM] float32
//   in1: mask_indices [B, M]      int32
//   in2: emb_mask     [1, DIM]    float32
// out: masked_x [B*N*DIM] floats (+ mask_indices as floats if room).

#define DIM      256
#define N_FIX    8192
#define ROWS_PB  128    // rows per block; 128 flags = 4 uint32
#define THREADS  512    // 8 rows in parallel (64 thr/row); scan in ONE iteration
#define UNROLL   8      // 8 float4 in flight per thread (32 staging regs)

__global__ void __launch_bounds__(THREADS)
fused_mask_kernel(const float* __restrict__ x,
                  const int*   __restrict__ mask_indices,
                  const float* __restrict__ emb_mask,
                  float*       __restrict__ out,
                  float*       __restrict__ out_idx,   // may be null
                  int M, int blocks_per_batch)
{
    __shared__ uint32_t fl[ROWS_PB / 32];   // 4 words

    const int tid = threadIdx.x;
    const int b   = blockIdx.x / blocks_per_batch;
    const int blk = blockIdx.x % blocks_per_batch;
    const int r0  = blk * ROWS_PB;

    if (tid < ROWS_PB / 32) fl[tid] = 0;
    __syncthreads();

    // Vectorized scan: int4 = 4 indices per load; M4=307 < 512 threads
    // -> single iteration per block.
    const int* idx_row = mask_indices + (size_t)b * M;
    const int M4 = M >> 2;                       // 307 for M=1228
    const int4* idx4 = reinterpret_cast<const int4*>(idx_row);
    const bool emit = (blk == 0) && (out_idx != nullptr);

    for (int i = tid; i < M4; i += THREADS) {
        int4 q = __ldg(&idx4[i]);
        int l0 = q.x - r0, l1 = q.y - r0, l2 = q.z - r0, l3 = q.w - r0;
        if ((unsigned)l0 < (unsigned)ROWS_PB) atomicOr(&fl[l0 >> 5], 1u << (l0 & 31));
        if ((unsigned)l1 < (unsigned)ROWS_PB) atomicOr(&fl[l1 >> 5], 1u << (l1 & 31));
        if ((unsigned)l2 < (unsigned)ROWS_PB) atomicOr(&fl[l2 >> 5], 1u << (l2 & 31));
        if ((unsigned)l3 < (unsigned)ROWS_PB) atomicOr(&fl[l3 >> 5], 1u << (l3 & 31));
        if (emit) {
            float4 f = make_float4((float)q.x, (float)q.y, (float)q.z, (float)q.w);
            reinterpret_cast<float4*>(out_idx + (size_t)b * M)[i] = f;
        }
    }
    // remainder (M % 4) — none for M=1228, but stay general
    for (int i = (M4 << 2) + tid; i < M; i += THREADS) {
        int idx = idx_row[i];
        int local = idx - r0;
        if ((unsigned)local < (unsigned)ROWS_PB)
            atomicOr(&fl[local >> 5], 1u << (local & 31));
        if (emit) out_idx[(size_t)b * M + i] = (float)idx;
    }
    __syncthreads();

    // bitmask into registers (broadcast LDS, conflict-free)
    uint32_t fw[ROWS_PB / 32];
    #pragma unroll
    for (int w = 0; w < ROWS_PB / 32; ++w) fw[w] = fl[w];

    const int sub  = tid >> 6;        // 0..7: row lane within a group of 8 rows
    const int col4 = tid & 63;        // float4 lane within row

    const float4 emb = reinterpret_cast<const float4*>(emb_mask)[col4];

    const size_t base = ((size_t)b * N_FIX + r0) * (DIM / 4);
    const float4* __restrict__ src = reinterpret_cast<const float4*>(x) + base;
    float4*       __restrict__ dst = reinterpret_cast<float4*>(out)     + base;

    // 16 row-iterations per thread: two direct 8-wide load/store batches
    // (max MLP, fully static addressing) — identical profile to the best
    // measured main loop (R13).
    #pragma unroll
    for (int it = 0; it < ROWS_PB / 8; it += UNROLL) {
        float4 v[UNROLL];
        #pragma unroll
        for (int u = 0; u < UNROLL; ++u) {
            const int row = (it + u) * 8 + sub;
            const size_t off = (size_t)row * (DIM / 4) + col4;
            const bool masked = (fw[row >> 5] >> (row & 31)) & 1u;
            v[u] = masked ? emb : __ldcs(&src[off]);
        }
        #pragma unroll
        for (int u = 0; u < UNROLL; ++u) {
            const int row = (it + u) * 8 + sub;
            const size_t off = (size_t)row * (DIM / 4) + col4;
            __stcs(&dst[off], v[u]);
        }
    }
}

extern "C" void kernel_launch(void* const* d_in, const int* in_sizes, int n_in,
                              void* d_out, int out_size)
{
    const float* x            = (const float*)d_in[0];
    const int*   mask_indices = (const int*)d_in[1];
    const float* emb_mask     = (const float*)d_in[2];
    float*       out          = (float*)d_out;

    const int x_elems   = in_sizes[0];          // B*N*DIM
    const int idx_elems = in_sizes[1];          // B*M
    const int BN        = x_elems / DIM;        // B*N
    const int B         = BN / N_FIX;
    const int M         = idx_elems / B;

    float* out_idx = (out_size >= x_elems + idx_elems)
                   ? (out + x_elems) : nullptr;

    const int blocks_per_batch = N_FIX / ROWS_PB;   // 64
    fused_mask_kernel<<<B * blocks_per_batch, THREADS>>>(
        x, mask_indices, emb_mask, out, out_idx, M, blocks_per_batch);
}